// round 15
// baseline (speedup 1.0000x reference)
#include <cuda_runtime.h>
#include <cstdint>

#define Bn   64
#define Tn   512
#define Dn   128
#define Hn   256
#define G4H  1024

typedef unsigned long long ull;
#define AMASK 0x7FFFFFFF7FFFFFFFULL

// Packed input projection: (v, m, r, _) per [t*64+b][4H]
__device__ float4 g_pxq[(size_t)Tn * Bn * G4H];

__device__ __forceinline__ ull pk2(float x) {
    ull r; asm("mov.b64 %0, {%1, %1};" : "=l"(r) : "f"(x)); return r;
}
__device__ __forceinline__ ull pk2u(unsigned x) {
    return ((ull)x << 32) | (ull)x;
}
__device__ __forceinline__ ull pkf2(float lo, float hi) {
    ull r; asm("mov.b64 %0, {%1, %2};" : "=l"(r) : "f"(lo), "f"(hi)); return r;
}
__device__ __forceinline__ void fma2(ull& d, ull a, ull b) {
    asm("fma.rn.f32x2 %0, %1, %2, %0;" : "+l"(d) : "l"(a), "l"(b));
}
__device__ __forceinline__ float2 unp(ull v) {
    float2 f; asm("mov.b64 {%0, %1}, %2;" : "=f"(f.x), "=f"(f.y) : "l"(v)); return f;
}
__device__ __forceinline__ uint32_t smem_u32(const void* p) {
    uint32_t a;
    asm("{ .reg .u64 t; cvta.to.shared.u64 t, %1; cvt.u32.u64 %0, t; }"
        : "=r"(a) : "l"(p));
    return a;
}
__device__ __forceinline__ uint32_t mapa_rank(uint32_t addr, uint32_t rank) {
    uint32_t r;
    asm("mapa.shared::cluster.u32 %0, %1, %2;" : "=r"(r) : "r"(addr), "r"(rank));
    return r;
}
__device__ __forceinline__ void st_cl64(uint32_t addr, ull v) {          // weak push
    asm volatile("st.shared::cluster.b64 [%0], %1;" :: "r"(addr), "l"(v) : "memory");
}
__device__ __forceinline__ void st_cl64_rel(uint32_t addr, ull v) {      // tag push
    asm volatile("st.release.cluster.shared::cluster.b64 [%0], %1;"
                 :: "r"(addr), "l"(v) : "memory");
}
__device__ __forceinline__ ull ld_acq_sh(uint32_t addr) {                // local poll
    ull v;
    asm volatile("ld.acquire.cluster.shared::cta.b64 %0, [%1];"
                 : "=l"(v) : "r"(addr) : "memory");
    return v;
}
__device__ __forceinline__ ull lds64(uint32_t addr) {
    ull v; asm volatile("ld.shared.b64 %0, [%1];" : "=l"(v) : "r"(addr));
    return v;
}

// ---------------------------------------------------------------------------
// Phase 1: Px = x @ W_ih^T (v@W, m@W, r@|W|), bias folded, packed float4 out.
// (unchanged — proven)
// ---------------------------------------------------------------------------
#define WT1_PITCH 132

__global__ void __launch_bounds__(256, 1) lstm_phase1(
    const float* __restrict__ xv, const float* __restrict__ xl,
    const float* __restrict__ xu, const float* __restrict__ Wih,
    const float* __restrict__ bias)
{
    extern __shared__ float sm1[];
    float4* xs  = (float4*)sm1;                 // [32][128] (v, m, r, 0)
    float*  wt1 = (float*)(xs + 32 * 128);      // [128][132]

    const int tid  = threadIdx.x;
    const int lane = tid & 31;
    const int wp   = tid >> 5;
    const int tb0  = blockIdx.x * 32;
    const int t0   = tb0 >> 6;
    const int b0   = tb0 & 63;
    const int j0   = blockIdx.y * 128;

    for (int idx = tid; idx < 32 * 128; idx += 256) {
        int rr = idx >> 7, d = idx & 127;
        size_t a = ((size_t)(b0 + rr) * Tn + t0) * Dn + d;
        float v = xv[a], l = xl[a], u = xu[a];
        xs[rr * 128 + d] = make_float4(v, 0.5f * (l + u), 0.5f * (u - l), 0.f);
    }
#pragma unroll
    for (int i = 0; i < 4; i++) {
        int cq = wp + 8 * i;
#pragma unroll
        for (int j = 0; j < 4; j++) {
            int k = j * 32 + lane;
            float w0 = Wih[(size_t)(j0 + 4 * cq + 0) * Dn + k];
            float w1 = Wih[(size_t)(j0 + 4 * cq + 1) * Dn + k];
            float w2 = Wih[(size_t)(j0 + 4 * cq + 2) * Dn + k];
            float w3 = Wih[(size_t)(j0 + 4 * cq + 3) * Dn + k];
            *(float4*)&wt1[k * WT1_PITCH + 4 * cq] = make_float4(w0, w1, w2, w3);
        }
    }
    __syncthreads();

    const int r0 = wp * 4;
    const int c0 = lane * 4;
    ull A[4][6];
#pragma unroll
    for (int r = 0; r < 4; r++)
#pragma unroll
        for (int q = 0; q < 6; q++) A[r][q] = 0ULL;

#pragma unroll 4
    for (int k = 0; k < 128; k++) {
        ulonglong2 uw = *(ulonglong2*)&wt1[k * WT1_PITCH + c0];
        ull wa0 = uw.x & AMASK, wa1 = uw.y & AMASK;
#pragma unroll
        for (int r = 0; r < 4; r++) {
            float4 h = xs[(r0 + r) * 128 + k];
            ull vv = pk2(h.x), mm = pk2(h.y), rr = pk2(h.z);
            fma2(A[r][0], vv, uw.x); fma2(A[r][1], vv, uw.y);
            fma2(A[r][2], mm, uw.x); fma2(A[r][3], mm, uw.y);
            fma2(A[r][4], rr, wa0);  fma2(A[r][5], rr, wa1);
        }
    }

    float4 b4 = *(const float4*)&bias[j0 + c0];
#pragma unroll
    for (int r = 0; r < 4; r++) {
        size_t ob = (size_t)(tb0 + r0 + r) * G4H + j0 + c0;
        float2 v01 = unp(A[r][0]), v23 = unp(A[r][1]);
        float2 m01 = unp(A[r][2]), m23 = unp(A[r][3]);
        float2 q01 = unp(A[r][4]), q23 = unp(A[r][5]);
        g_pxq[ob + 0] = make_float4(v01.x + b4.x, m01.x + b4.x, q01.x, 0.f);
        g_pxq[ob + 1] = make_float4(v01.y + b4.y, m01.y + b4.y, q01.y, 0.f);
        g_pxq[ob + 2] = make_float4(v23.x + b4.z, m23.x + b4.z, q23.x, 0.f);
        g_pxq[ob + 3] = make_float4(v23.y + b4.w, m23.y + b4.w, q23.y, 0.f);
    }
}

// ---------------------------------------------------------------------------
// Phase 2: persistent recurrent interval-LSTM, DSMEM push exchange.
// 16 clusters x 8 CTAs (one cluster per batch-group; CTA = 32 hidden units).
// NO per-step cluster.sync. Producer pushes each h element into ALL 8 peers'
// SMEM staging: weak st {v,m} then st.release {tag|r} (same thread orders it;
// 8B atomics untorn). Consumer spins on ITS OWN SMEM (ld.acquire local,
// ~30cyc/retry vs ~600 L2 RT), then copies to its private hvm/hr scratch.
// Staging parity-buffered; overwrite-safe by <=1-step skew induction.
// Replay-safe trivially: all sync state is SMEM, zeroed each launch.
// GEMM: warp (rp,kq) = rows {2rp,2rp+1} x 128 cols x 64-k quarter (proven).
// ---------------------------------------------------------------------------
#define WT2_PITCH 132

struct I3 { float v, l, u; };

__device__ __forceinline__ float sigm(float x)   { return 1.0f / (1.0f + __expf(-x)); }
__device__ __forceinline__ float tanh_f(float x) { return 1.0f - 2.0f / (1.0f + __expf(2.0f * x)); }
__device__ __forceinline__ I3 imul(I3 a, I3 b) {
    float p1 = a.l * b.l, p2 = a.l * b.u, p3 = a.u * b.l, p4 = a.u * b.u;
    I3 o;
    o.v = a.v * b.v;
    o.l = fminf(fminf(p1, p2), fminf(p3, p4));
    o.u = fmaxf(fmaxf(p1, p2), fmaxf(p3, p4));
    return o;
}

// SMEM offsets (bytes)
#define OFF_WT    0
#define SM_WT_B   (256 * WT2_PITCH * 4)        // 135168
#define OFF_SVM   (OFF_WT + SM_WT_B)           // staging {v,m}:   ull[2][1024]
#define SM_SVM_B  (2 * 1024 * 8)               // 16384
#define OFF_STR   (OFF_SVM + SM_SVM_B)         // staging {tag|r}: ull[2][1024]
#define SM_STR_B  (2 * 1024 * 8)               // 16384
#define OFF_HVM   (OFF_STR + SM_STR_B)         // scratch {v,v,m,m}: ulonglong2[4][256]
#define SM_HVM_B  (4 * 256 * 16)               // 16384
#define OFF_HR    (OFF_HVM + SM_HVM_B)         // scratch {r,r}: ull[4][256]
#define SM_HR_B   (4 * 256 * 8)                // 8192
#define OFF_GBUF  (OFF_HR + SM_HR_B)           // partials: float4[4][4][128]
#define SM_GBUF_B (4 * 4 * 128 * 16)           // 32768
#define SM2_TOTAL (OFF_GBUF + SM_GBUF_B)       // 225280

__global__ void __cluster_dims__(8, 1, 1) __launch_bounds__(256, 1)
lstm_phase2(const float* __restrict__ Whh, float* __restrict__ out)
{
    extern __shared__ char sm2c[];
    float*      wt   = (float*)(sm2c + OFF_WT);          // [256][132]
    ulonglong2* hvm  = (ulonglong2*)(sm2c + OFF_HVM);    // [4][256]
    ull*        hr   = (ull*)(sm2c + OFF_HR);            // [4][256]
    float4*     gbuf = (float4*)(sm2c + OFF_GBUF);       // [4 kq][4 row][128]
    ull*        svm  = (ull*)(sm2c + OFF_SVM);
    ull*        str0 = (ull*)(sm2c + OFF_STR);

    const uint32_t sbase = smem_u32(sm2c);
    const int tid  = threadIdx.x;
    const int lane = tid & 31;
    const int wp   = tid >> 5;
    const int grp  = blockIdx.x >> 3;
    const int cta  = blockIdx.x & 7;      // == cluster rank
    const int hbase = cta * 32;
    const int bbase = grp * 4;

    // W_hh slice transposed: wt[k][c], c = g*32 + j
#pragma unroll
    for (int i = 0; i < 4; i++) {
        int cq = wp + 8 * i;
#pragma unroll
        for (int j = 0; j < 8; j++) {
            int k = j * 32 + lane;
            float w[4];
#pragma unroll
            for (int q = 0; q < 4; q++) {
                int c = 4 * cq + q;
                int g = c >> 5, jj = c & 31;
                w[q] = Whh[(size_t)(g * 256 + hbase + jj) * Hn + k];
            }
            *(float4*)&wt[k * WT2_PITCH + 4 * cq] = make_float4(w[0], w[1], w[2], w[3]);
        }
    }
    // Zero scratch + staging (per-launch state -> replay-safe by construction)
    for (int i = tid; i < 4 * 256; i += 256) {
        hvm[i] = make_ulonglong2(0ULL, 0ULL);
        hr[i]  = 0ULL;
    }
    for (int i = tid; i < 2 * 1024; i += 256) { svm[i] = 0ULL; str0[i] = 0ULL; }
    __syncthreads();
    // All cluster CTAs' staging must be zeroed before any peer push lands.
    asm volatile("barrier.cluster.arrive.aligned;" ::: "memory");
    asm volatile("barrier.cluster.wait.aligned;"  ::: "memory");

    const int rp   = wp >> 2;       // row pair 0..1
    const int kq   = wp & 3;        // k quarter 0..3
    const int kb   = kq * 64;
    const int c0   = lane * 4;      // 4 cols per thread
    const int erow = tid >> 5;      // elementwise row (tid<128)
    const int ej   = tid & 31;
    float cv = 0.f, cl = 0.f, cu = 0.f;

    // t-invariant pull geometry: this warp's private region is
    // slices {2kq,2kq+1} x rows {2rp,2rp+1}, 4 elements per lane.
    int off[4], srow[4], skk[4];
#pragma unroll
    for (int p = 0; p < 4; p++) {
        int idx = p * 32 + lane;            // 0..127
        int s   = idx >> 6;                 // slice select 0..1
        int rr  = (idx >> 5) & 1;           // row select 0..1
        int j   = idx & 31;
        off[p]  = (2 * kq + s) * 128 + (2 * rp + rr) * 32 + j;
        srow[p] = 2 * rp + rr;
        skk[p]  = (2 * kq + s) * 32 + j;
    }

    const size_t PLANE = (size_t)Bn * Tn * Hn;

    for (int t = 0; t < Tn; t++) {
        // Px prefetch (epilogue threads; hides DRAM under poll/GEMM)
        float4 P[4];
        if (tid < 128) {
            size_t base = ((size_t)t * 64 + bbase + erow) * G4H + hbase + ej;
#pragma unroll
            for (int g = 0; g < 4; g++) P[g] = g_pxq[base + g * 256];
        }

        if (t > 0) {
            // Local poll: tag word {tag|r} in OWN SMEM; want tag == t.
            // Slot values: stale t-2 or fresh t (skew <= 1 step; t+2 write
            // needs every consumer's t+1 push first -> impossible here).
            const unsigned want = (unsigned)t;
            const int par = (t - 1) & 1;
            const uint32_t aV = sbase + OFF_SVM + (uint32_t)par * 8192;
            const uint32_t aT = sbase + OFF_STR + (uint32_t)par * 8192;
            ull vr[4];
#pragma unroll
            for (int p = 0; p < 4; p++) vr[p] = ld_acq_sh(aT + off[p] * 8);
#pragma unroll
            for (int p = 0; p < 4; p++) {
                while ((unsigned)(vr[p] >> 32) != want)
                    vr[p] = ld_acq_sh(aT + off[p] * 8);
            }
            // Data words ordered by the acquire; copy into private scratch.
#pragma unroll
            for (int p = 0; p < 4; p++) {
                ull vm = lds64(aV + off[p] * 8);            // {v, m}
                float2 f = unp(vm);
                hvm[srow[p] * 256 + skk[p]] = make_ulonglong2(pk2(f.x), pk2(f.y));
                hr[srow[p] * 256 + skk[p]]  = pk2u((unsigned)vr[p]);
            }
            __syncwarp();
        }

        // GEMM: warp covers rows {2rp, 2rp+1} x 128 cols x k in [kb, kb+64)
        ull A[2][6];
#pragma unroll
        for (int r = 0; r < 2; r++)
#pragma unroll
            for (int q = 0; q < 6; q++) A[r][q] = 0ULL;

#pragma unroll 8
        for (int kk = 0; kk < 64; kk++) {
            const int k = kb + kk;
            ulonglong2 w2 = *(const ulonglong2*)&wt[k * WT2_PITCH + c0];
            ull wa0 = w2.x & AMASK, wa1 = w2.y & AMASK;
#pragma unroll
            for (int r2 = 0; r2 < 2; r2++) {
                const int r = rp * 2 + r2;
                ulonglong2 h2 = hvm[r * 256 + k];
                ull h3 = hr[r * 256 + k];
                fma2(A[r2][0], h2.x, w2.x); fma2(A[r2][1], h2.x, w2.y);
                fma2(A[r2][2], h2.y, w2.x); fma2(A[r2][3], h2.y, w2.y);
                fma2(A[r2][4], h3, wa0);    fma2(A[r2][5], h3, wa1);
            }
        }

        // Partials: warp (rp,kq) owns disjoint slot rows.
        {
            float4* gs = gbuf + ((size_t)kq * 4 + rp * 2) * 128;
#pragma unroll
            for (int r2 = 0; r2 < 2; r2++) {
                float2 v01 = unp(A[r2][0]), v23 = unp(A[r2][1]);
                float2 m01 = unp(A[r2][2]), m23 = unp(A[r2][3]);
                float2 q01 = unp(A[r2][4]), q23 = unp(A[r2][5]);
                float4* gp = gs + r2 * 128 + c0;
                gp[0] = make_float4(v01.x, m01.x, q01.x, 0.f);
                gp[1] = make_float4(v01.y, m01.y, q01.y, 0.f);
                gp[2] = make_float4(v23.x, m23.x, q23.x, 0.f);
                gp[3] = make_float4(v23.y, m23.y, q23.y, 0.f);
            }
        }
        __syncthreads();                    // partials visible to epilogue

        if (tid < 128) {
            I3 gate[4];
#pragma unroll
            for (int g = 0; g < 4; g++) {
                int col = g * 32 + ej;
                float v = P[g].x, m = P[g].y, rr = P[g].z;
#pragma unroll
                for (int s = 0; s < 4; s++) {          // sum 4 k-quarters
                    float4 gs = gbuf[((size_t)s * 4 + erow) * 128 + col];
                    v += gs.x; m += gs.y; rr += gs.z;
                }
                gate[g].v = v; gate[g].l = m - rr; gate[g].u = m + rr;
            }
            I3 ig = { sigm(gate[0].v),   sigm(gate[0].l),   sigm(gate[0].u) };
            I3 fg = { sigm(gate[1].v),   sigm(gate[1].l),   sigm(gate[1].u) };
            I3 gg = { tanh_f(gate[2].v), tanh_f(gate[2].l), tanh_f(gate[2].u) };
            I3 og = { sigm(gate[3].v),   sigm(gate[3].l),   sigm(gate[3].u) };

            I3 cold = { cv, cl, cu };
            I3 fc  = imul(fg, cold);
            I3 igg = imul(ig, gg);
            I3 cn  = { fc.v + igg.v, fc.l + igg.l, fc.u + igg.u };
            I3 tc  = { tanh_f(cn.v), tanh_f(cn.l), tanh_f(cn.u) };
            I3 hn  = imul(og, tc);
            cv = cn.v; cl = cn.l; cu = cn.u;

            size_t ob = ((size_t)(bbase + erow) * Tn + t) * Hn + hbase + ej;
            out[ob]             = hn.v;
            out[ob + PLANE]     = hn.l;
            out[ob + 2 * PLANE] = hn.u;

            if (t < Tn - 1) {
                // Push h(t) to all 8 cluster CTAs: weak {v,m} then release
                // {tag|r} per rank (same-thread order; 8B atomic, untorn).
                float hm  = 0.5f * (hn.l + hn.u);
                float hrr = 0.5f * (hn.u - hn.l);
                int par = t & 1;
                int idx = cta * 128 + erow * 32 + ej;   // staging slot
                uint32_t aV = sbase + OFF_SVM + ((uint32_t)par * 1024 + idx) * 8;
                uint32_t aT = sbase + OFF_STR + ((uint32_t)par * 1024 + idx) * 8;
                ull vm = pkf2(hn.v, hm);
                ull tr = ((ull)(unsigned)(t + 1) << 32) | (ull)__float_as_uint(hrr);
#pragma unroll
                for (unsigned rk = 0; rk < 8; rk++) {
                    st_cl64(mapa_rank(aV, rk), vm);
                    st_cl64_rel(mapa_rank(aT, rk), tr);
                }
            }
        }
        __syncthreads();   // epilogue done reading gbuf before next partials
    }

    // Keep all cluster CTAs alive until every peer push has landed.
    asm volatile("barrier.cluster.arrive.aligned;" ::: "memory");
    asm volatile("barrier.cluster.wait.aligned;"  ::: "memory");
}

// ---------------------------------------------------------------------------
extern "C" void kernel_launch(void* const* d_in, const int* in_sizes, int n_in,
                              void* d_out, int out_size)
{
    const float* xv   = (const float*)d_in[0];
    const float* xl   = (const float*)d_in[1];
    const float* xu   = (const float*)d_in[2];
    const float* Wih  = (const float*)d_in[3];
    const float* Whh  = (const float*)d_in[4];
    const float* bias = (const float*)d_in[5];
    float* out = (float*)d_out;

    const int smem1 = 32 * 128 * (int)sizeof(float4)
                    + 128 * WT1_PITCH * (int)sizeof(float);

    cudaFuncSetAttribute(lstm_phase1, cudaFuncAttributeMaxDynamicSharedMemorySize, smem1);
    cudaFuncSetAttribute(lstm_phase2, cudaFuncAttributeMaxDynamicSharedMemorySize, SM2_TOTAL);

    lstm_phase1<<<dim3(1024, 8, 1), 256, smem1>>>(xv, xl, xu, Wih, bias);
    // 16 clusters x 8 CTAs = 128 CTAs, one wave, no per-step cluster sync
    lstm_phase2<<<128, 256, SM2_TOTAL>>>(Whh, out);
}

// round 16
// speedup vs baseline: 1.8106x; 1.8106x over previous
#include <cuda_runtime.h>
#include <cstdint>

#define Bn   64
#define Tn   512
#define Dn   128
#define Hn   256
#define G4H  1024

typedef unsigned long long ull;
#define AMASK 0x7FFFFFFF7FFFFFFFULL

// Packed input projection: (v, m, r, _) per [t*64+b][4H]
__device__ float4 g_pxq[(size_t)Tn * Bn * G4H];
// h staging through L2: three SELF-VALIDATING words per element:
//   word = (tag << 32) | float_bits.  8B relaxed atomics are untorn.
__device__ ull g_sv[2][16][8][128];
__device__ ull g_sm[2][16][8][128];
__device__ ull g_sr[2][16][8][128];

__device__ __forceinline__ ull pk2(float x) {
    ull r; asm("mov.b64 %0, {%1, %1};" : "=l"(r) : "f"(x)); return r;
}
__device__ __forceinline__ ull pk2u(unsigned x) {
    return ((ull)x << 32) | (ull)x;
}
__device__ __forceinline__ void fma2(ull& d, ull a, ull b) {
    asm("fma.rn.f32x2 %0, %1, %2, %0;" : "+l"(d) : "l"(a), "l"(b));
}
__device__ __forceinline__ float2 unp(ull v) {
    float2 f; asm("mov.b64 {%0, %1}, %2;" : "=f"(f.x), "=f"(f.y) : "l"(v)); return f;
}
__device__ __forceinline__ ull ld_rx64(const ull* p) {
    ull v; asm volatile("ld.relaxed.gpu.global.b64 %0, [%1];" : "=l"(v) : "l"(p) : "memory");
    return v;
}
__device__ __forceinline__ void st_rx64(ull* p, ull v) {
    asm volatile("st.relaxed.gpu.global.b64 [%0], %1;" :: "l"(p), "l"(v) : "memory");
}

// ---------------------------------------------------------------------------
// Phase 1: Px = x @ W_ih^T (v@W, m@W, r@|W|), bias folded, packed float4 out.
// (unchanged — proven)
// ---------------------------------------------------------------------------
#define WT1_PITCH 132

__global__ void __launch_bounds__(256, 1) lstm_phase1(
    const float* __restrict__ xv, const float* __restrict__ xl,
    const float* __restrict__ xu, const float* __restrict__ Wih,
    const float* __restrict__ bias)
{
    extern __shared__ float sm1[];
    float4* xs  = (float4*)sm1;                 // [32][128] (v, m, r, 0)
    float*  wt1 = (float*)(xs + 32 * 128);      // [128][132]

    const int tid  = threadIdx.x;
    const int lane = tid & 31;
    const int wp   = tid >> 5;
    const int tb0  = blockIdx.x * 32;
    const int t0   = tb0 >> 6;
    const int b0   = tb0 & 63;
    const int j0   = blockIdx.y * 128;

    for (int idx = tid; idx < 32 * 128; idx += 256) {
        int rr = idx >> 7, d = idx & 127;
        size_t a = ((size_t)(b0 + rr) * Tn + t0) * Dn + d;
        float v = xv[a], l = xl[a], u = xu[a];
        xs[rr * 128 + d] = make_float4(v, 0.5f * (l + u), 0.5f * (u - l), 0.f);
    }
#pragma unroll
    for (int i = 0; i < 4; i++) {
        int cq = wp + 8 * i;
#pragma unroll
        for (int j = 0; j < 4; j++) {
            int k = j * 32 + lane;
            float w0 = Wih[(size_t)(j0 + 4 * cq + 0) * Dn + k];
            float w1 = Wih[(size_t)(j0 + 4 * cq + 1) * Dn + k];
            float w2 = Wih[(size_t)(j0 + 4 * cq + 2) * Dn + k];
            float w3 = Wih[(size_t)(j0 + 4 * cq + 3) * Dn + k];
            *(float4*)&wt1[k * WT1_PITCH + 4 * cq] = make_float4(w0, w1, w2, w3);
        }
    }
    __syncthreads();

    const int r0 = wp * 4;
    const int c0 = lane * 4;
    ull A[4][6];
#pragma unroll
    for (int r = 0; r < 4; r++)
#pragma unroll
        for (int q = 0; q < 6; q++) A[r][q] = 0ULL;

#pragma unroll 4
    for (int k = 0; k < 128; k++) {
        ulonglong2 uw = *(ulonglong2*)&wt1[k * WT1_PITCH + c0];
        ull wa0 = uw.x & AMASK, wa1 = uw.y & AMASK;
#pragma unroll
        for (int r = 0; r < 4; r++) {
            float4 h = xs[(r0 + r) * 128 + k];
            ull vv = pk2(h.x), mm = pk2(h.y), rr = pk2(h.z);
            fma2(A[r][0], vv, uw.x); fma2(A[r][1], vv, uw.y);
            fma2(A[r][2], mm, uw.x); fma2(A[r][3], mm, uw.y);
            fma2(A[r][4], rr, wa0);  fma2(A[r][5], rr, wa1);
        }
    }

    float4 b4 = *(const float4*)&bias[j0 + c0];
#pragma unroll
    for (int r = 0; r < 4; r++) {
        size_t ob = (size_t)(tb0 + r0 + r) * G4H + j0 + c0;
        float2 v01 = unp(A[r][0]), v23 = unp(A[r][1]);
        float2 m01 = unp(A[r][2]), m23 = unp(A[r][3]);
        float2 q01 = unp(A[r][4]), q23 = unp(A[r][5]);
        g_pxq[ob + 0] = make_float4(v01.x + b4.x, m01.x + b4.x, q01.x, 0.f);
        g_pxq[ob + 1] = make_float4(v01.y + b4.y, m01.y + b4.y, q01.y, 0.f);
        g_pxq[ob + 2] = make_float4(v23.x + b4.z, m23.x + b4.z, q23.x, 0.f);
        g_pxq[ob + 3] = make_float4(v23.y + b4.w, m23.y + b4.w, q23.y, 0.f);
    }
}

// ---------------------------------------------------------------------------
// Phase 2: persistent recurrent interval-LSTM, single-trip tagged exchange
// (R14 transport, frozen). 128 CTAs = 16 groups x 8 CTAs.
// NEW GEMM mapping: warp wp = ALL 4 rows x 128 cols x 32-k slice [wp*32,..):
// weights read ONCE per (k,col) -> GEMM wavefronts 4096 -> 3072 (FMA-balanced).
// Warp wp's pull region = producer slice wp x 4 rows (single producer!).
// 8 disjoint partial sets, single-stage; 2 barriers/step.
// ---------------------------------------------------------------------------
#define WT2_PITCH 132

struct I3 { float v, l, u; };

__device__ __forceinline__ float sigm(float x)   { return 1.0f / (1.0f + __expf(-x)); }
__device__ __forceinline__ float tanh_f(float x) { return 1.0f - 2.0f / (1.0f + __expf(2.0f * x)); }
__device__ __forceinline__ I3 imul(I3 a, I3 b) {
    float p1 = a.l * b.l, p2 = a.l * b.u, p3 = a.u * b.l, p4 = a.u * b.u;
    I3 o;
    o.v = a.v * b.v;
    o.l = fminf(fminf(p1, p2), fminf(p3, p4));
    o.u = fmaxf(fmaxf(p1, p2), fmaxf(p3, p4));
    return o;
}

#define SM_WT_BYTES   (256 * WT2_PITCH * 4)            // 135168
#define SM_HVM_BYTES  (4 * 256 * 16)                   // 16384
#define SM_HR_BYTES   (4 * 256 * 8)                    // 8192
#define SM_GBUF_BYTES (8 * 4 * 128 * 16)               // 65536 ([set][row][col])
#define SM2_TOTAL     (SM_WT_BYTES + SM_HVM_BYTES + SM_HR_BYTES + SM_GBUF_BYTES) // 225280

__global__ void __launch_bounds__(256, 1)
lstm_phase2(const float* __restrict__ Whh, float* __restrict__ out)
{
    extern __shared__ char sm2c[];
    float*      wt   = (float*)sm2c;                                    // [256][132]
    ulonglong2* hvm  = (ulonglong2*)(sm2c + SM_WT_BYTES);               // [4][256] {v,v,m,m}
    ull*        hr   = (ull*)(sm2c + SM_WT_BYTES + SM_HVM_BYTES);       // [4][256] {r,r}
    float4*     gbuf = (float4*)(sm2c + SM_WT_BYTES + SM_HVM_BYTES + SM_HR_BYTES); // [8][4][128]

    const int tid  = threadIdx.x;
    const int lane = tid & 31;
    const int wp   = tid >> 5;
    const int grp  = blockIdx.x >> 3;
    const int cta  = blockIdx.x & 7;
    const int hbase = cta * 32;
    const int bbase = grp * 4;

    // W_hh slice transposed: wt[k][c], c = g*32 + j
#pragma unroll
    for (int i = 0; i < 4; i++) {
        int cq = wp + 8 * i;
#pragma unroll
        for (int j = 0; j < 8; j++) {
            int k = j * 32 + lane;
            float w[4];
#pragma unroll
            for (int q = 0; q < 4; q++) {
                int c = 4 * cq + q;
                int g = c >> 5, jj = c & 31;
                w[q] = Whh[(size_t)(g * 256 + hbase + jj) * Hn + k];
            }
            *(float4*)&wt[k * WT2_PITCH + 4 * cq] = make_float4(w[0], w[1], w[2], w[3]);
        }
    }
    for (int i = tid; i < 4 * 256; i += 256) {
        hvm[i] = make_ulonglong2(0ULL, 0ULL);
        hr[i]  = 0ULL;
    }
    __syncthreads();

    const int kb   = wp * 32;       // warp k-slice == producer slice wp
    const int c0   = lane * 4;      // 4 cols per thread
    const int erow = tid >> 5;      // elementwise row (tid<128)
    const int ej   = tid & 31;
    float cv = 0.f, cl = 0.f, cu = 0.f;

    // t-invariant pull geometry: warp wp needs slice wp x rows 0..3,
    // 128 elements, 4 per lane: element p -> (row=p, j=lane).
    int off[4];
#pragma unroll
    for (int p = 0; p < 4; p++) off[p] = wp * 128 + p * 32 + lane;
    const ull* baseV[2] = { &g_sv[0][grp][0][0], &g_sv[1][grp][0][0] };
    const ull* baseM[2] = { &g_sm[0][grp][0][0], &g_sm[1][grp][0][0] };
    const ull* baseR[2] = { &g_sr[0][grp][0][0], &g_sr[1][grp][0][0] };

    const size_t PLANE = (size_t)Bn * Tn * Hn;

    for (int t = 0; t < Tn; t++) {
        // Px prefetch (epilogue warps only; hides DRAM under poll/GEMM)
        float4 P[4];
        if (tid < 128) {
            size_t base = ((size_t)t * 64 + bbase + erow) * G4H + hbase + ej;
#pragma unroll
            for (int g = 0; g < 4; g++) P[g] = g_pxq[base + g * 256];
        }

        if (t > 0) {
            // Single-trip poll+pull (R14-frozen): 12 relaxed loads up front,
            // spin per word until its tag == t. Untorn 8B words; validity
            // in-band -> no fences. Replay-safe (monotone per-slot tags;
            // the t-2 poll of the same slot forces this-launch overwrite).
            const unsigned want = (unsigned)t;
            const int par = (t - 1) & 1;
            const ull* sv = baseV[par];
            const ull* sm = baseM[par];
            const ull* sr = baseR[par];
            ull vv[4], vm[4], vr[4];
#pragma unroll
            for (int p = 0; p < 4; p++) {
                vv[p] = ld_rx64(sv + off[p]);
                vm[p] = ld_rx64(sm + off[p]);
                vr[p] = ld_rx64(sr + off[p]);
            }
#pragma unroll
            for (int p = 0; p < 4; p++) {
                while ((unsigned)(vv[p] >> 32) != want) vv[p] = ld_rx64(sv + off[p]);
                while ((unsigned)(vm[p] >> 32) != want) vm[p] = ld_rx64(sm + off[p]);
                while ((unsigned)(vr[p] >> 32) != want) vr[p] = ld_rx64(sr + off[p]);
            }
#pragma unroll
            for (int p = 0; p < 4; p++) {
                int k = kb + lane;                 // slice wp, element j=lane
                ulonglong2 pk;
                pk.x = pk2u((unsigned)vv[p]);
                pk.y = pk2u((unsigned)vm[p]);
                hvm[p * 256 + k] = pk;
                hr[p * 256 + k]  = pk2u((unsigned)vr[p]);
            }
            __syncwarp();   // pull visible warp-wide before GEMM
        }

        // GEMM: warp covers ALL 4 rows x 128 cols x k in [kb, kb+32)
        // (weights read once per (k,col) -> LDS-balanced with FMA)
        ull A[4][6];
#pragma unroll
        for (int r = 0; r < 4; r++)
#pragma unroll
            for (int q = 0; q < 6; q++) A[r][q] = 0ULL;

#pragma unroll 4
        for (int kk = 0; kk < 32; kk++) {
            const int k = kb + kk;
            ulonglong2 w2 = *(const ulonglong2*)&wt[k * WT2_PITCH + c0];
            ull wa0 = w2.x & AMASK, wa1 = w2.y & AMASK;
#pragma unroll
            for (int r = 0; r < 4; r++) {
                ulonglong2 h2 = hvm[r * 256 + k];
                ull h3 = hr[r * 256 + k];
                fma2(A[r][0], h2.x, w2.x); fma2(A[r][1], h2.x, w2.y);
                fma2(A[r][2], h2.y, w2.x); fma2(A[r][3], h2.y, w2.y);
                fma2(A[r][4], h3, wa0);    fma2(A[r][5], h3, wa1);
            }
        }

        // Single-stage partials: warp wp owns set wp (disjoint).
        {
            float4* gs = gbuf + (size_t)wp * 4 * 128;
#pragma unroll
            for (int r = 0; r < 4; r++) {
                float2 v01 = unp(A[r][0]), v23 = unp(A[r][1]);
                float2 m01 = unp(A[r][2]), m23 = unp(A[r][3]);
                float2 q01 = unp(A[r][4]), q23 = unp(A[r][5]);
                float4* gp = gs + r * 128 + c0;
                gp[0] = make_float4(v01.x, m01.x, q01.x, 0.f);
                gp[1] = make_float4(v01.y, m01.y, q01.y, 0.f);
                gp[2] = make_float4(v23.x, m23.x, q23.x, 0.f);
                gp[3] = make_float4(v23.y, m23.y, q23.y, 0.f);
            }
        }
        __syncthreads();                    // partials visible to epilogue

        if (tid < 128) {
            I3 gate[4];
#pragma unroll
            for (int g = 0; g < 4; g++) {
                int col = g * 32 + ej;
                float v = P[g].x, m = P[g].y, rr = P[g].z;
#pragma unroll
                for (int s = 0; s < 8; s++) {          // sum 8 k-slices
                    float4 gs = gbuf[((size_t)s * 4 + erow) * 128 + col];
                    v += gs.x; m += gs.y; rr += gs.z;
                }
                gate[g].v = v; gate[g].l = m - rr; gate[g].u = m + rr;
            }
            I3 ig = { sigm(gate[0].v),   sigm(gate[0].l),   sigm(gate[0].u) };
            I3 fg = { sigm(gate[1].v),   sigm(gate[1].l),   sigm(gate[1].u) };
            I3 gg = { tanh_f(gate[2].v), tanh_f(gate[2].l), tanh_f(gate[2].u) };
            I3 og = { sigm(gate[3].v),   sigm(gate[3].l),   sigm(gate[3].u) };

            I3 cold = { cv, cl, cu };
            I3 fc  = imul(fg, cold);
            I3 igg = imul(ig, gg);
            I3 cn  = { fc.v + igg.v, fc.l + igg.l, fc.u + igg.u };
            I3 tc  = { tanh_f(cn.v), tanh_f(cn.l), tanh_f(cn.u) };
            I3 hn  = imul(og, tc);
            cv = cn.v; cl = cn.l; cu = cn.u;

            size_t ob = ((size_t)(bbase + erow) * Tn + t) * Hn + hbase + ej;
            out[ob]             = hn.v;
            out[ob + PLANE]     = hn.l;
            out[ob + 2 * PLANE] = hn.u;

            if (t < Tn - 1) {
                // Publish h(t): three self-validating words, tag = t+1.
                int slot = erow * 32 + ej;
                float hm  = 0.5f * (hn.l + hn.u);
                float hrr = 0.5f * (hn.u - hn.l);
                ull tag = (ull)(unsigned)(t + 1) << 32;
                st_rx64(&g_sv[t & 1][grp][cta][slot], tag | __float_as_uint(hn.v));
                st_rx64(&g_sm[t & 1][grp][cta][slot], tag | __float_as_uint(hm));
                st_rx64(&g_sr[t & 1][grp][cta][slot], tag | __float_as_uint(hrr));
            }
        }
        __syncthreads();   // epilogue done reading gbuf before next partials
    }
}

// ---------------------------------------------------------------------------
extern "C" void kernel_launch(void* const* d_in, const int* in_sizes, int n_in,
                              void* d_out, int out_size)
{
    const float* xv   = (const float*)d_in[0];
    const float* xl   = (const float*)d_in[1];
    const float* xu   = (const float*)d_in[2];
    const float* Wih  = (const float*)d_in[3];
    const float* Whh  = (const float*)d_in[4];
    const float* bias = (const float*)d_in[5];
    float* out = (float*)d_out;

    const int smem1 = 32 * 128 * (int)sizeof(float4)
                    + 128 * WT1_PITCH * (int)sizeof(float);

    cudaFuncSetAttribute(lstm_phase1, cudaFuncAttributeMaxDynamicSharedMemorySize, smem1);
    cudaFuncSetAttribute(lstm_phase2, cudaFuncAttributeMaxDynamicSharedMemorySize, SM2_TOTAL);

    lstm_phase1<<<dim3(1024, 8, 1), 256, smem1>>>(xv, xl, xu, Wih, bias);
    lstm_phase2<<<128, 256, SM2_TOTAL>>>(Whh, out);
}

// round 17
// speedup vs baseline: 2.0597x; 1.1376x over previous
#include <cuda_runtime.h>
#include <cstdint>

#define Bn   64
#define Tn   512
#define Dn   128
#define Hn   256
#define G4H  1024

typedef unsigned long long ull;
#define AMASK 0x7FFFFFFF7FFFFFFFULL

// Packed input projection: (v, m, r, _) per [t*64+b][4H]
__device__ float4 g_pxq[(size_t)Tn * Bn * G4H];
// h staging through L2: three SELF-VALIDATING words per element:
//   word = (tag << 32) | float_bits.  8B relaxed atomics are untorn.
__device__ ull g_sv[2][16][8][128];
__device__ ull g_sm[2][16][8][128];
__device__ ull g_sr[2][16][8][128];

__device__ __forceinline__ ull pk2(float x) {
    ull r; asm("mov.b64 %0, {%1, %1};" : "=l"(r) : "f"(x)); return r;
}
__device__ __forceinline__ ull pk2u(unsigned x) {
    return ((ull)x << 32) | (ull)x;
}
__device__ __forceinline__ void fma2(ull& d, ull a, ull b) {
    asm("fma.rn.f32x2 %0, %1, %2, %0;" : "+l"(d) : "l"(a), "l"(b));
}
__device__ __forceinline__ float2 unp(ull v) {
    float2 f; asm("mov.b64 {%0, %1}, %2;" : "=f"(f.x), "=f"(f.y) : "l"(v)); return f;
}
__device__ __forceinline__ ull ld_rx64(const ull* p) {
    ull v; asm volatile("ld.relaxed.gpu.global.b64 %0, [%1];" : "=l"(v) : "l"(p) : "memory");
    return v;
}
__device__ __forceinline__ void st_rx64(ull* p, ull v) {
    asm volatile("st.relaxed.gpu.global.b64 [%0], %1;" :: "l"(p), "l"(v) : "memory");
}

// ---------------------------------------------------------------------------
// Phase 1: Px = x @ W_ih^T (v@W, m@W, r@|W|), bias folded, packed float4 out.
// R17: 16-row x-tiles -> SMEM 100KB -> 2 CTAs/SM (latency hiding).
// Thread = 2 rows x 4 cols, packed f32x2; W tile [128][132] unchanged.
// ---------------------------------------------------------------------------
#define WT1_PITCH 132

__global__ void __launch_bounds__(256, 2) lstm_phase1(
    const float* __restrict__ xv, const float* __restrict__ xl,
    const float* __restrict__ xu, const float* __restrict__ Wih,
    const float* __restrict__ bias)
{
    extern __shared__ float sm1[];
    float4* xs  = (float4*)sm1;                 // [16][128] (v, m, r, 0) = 32KB
    float*  wt1 = (float*)(xs + 16 * 128);      // [128][132] = 67.5KB

    const int tid  = threadIdx.x;
    const int lane = tid & 31;
    const int wp   = tid >> 5;
    const int tb0  = blockIdx.x * 16;           // 16 rows per block
    const int t0   = tb0 >> 6;
    const int b0   = tb0 & 63;                  // 16-aligned within 64 -> same t
    const int j0   = blockIdx.y * 128;

    // x tile -> (v, m, r): 2048 elements, 8 per thread
    for (int idx = tid; idx < 16 * 128; idx += 256) {
        int rr = idx >> 7, d = idx & 127;
        size_t a = ((size_t)(b0 + rr) * Tn + t0) * Dn + d;
        float v = xv[a], l = xl[a], u = xu[a];
        xs[rr * 128 + d] = make_float4(v, 0.5f * (l + u), 0.5f * (u - l), 0.f);
    }
    // W tile transposed: wt1[k][c]; lanes = consecutive k -> conflict-free
#pragma unroll
    for (int i = 0; i < 4; i++) {
        int cq = wp + 8 * i;
#pragma unroll
        for (int j = 0; j < 4; j++) {
            int k = j * 32 + lane;
            float w0 = Wih[(size_t)(j0 + 4 * cq + 0) * Dn + k];
            float w1 = Wih[(size_t)(j0 + 4 * cq + 1) * Dn + k];
            float w2 = Wih[(size_t)(j0 + 4 * cq + 2) * Dn + k];
            float w3 = Wih[(size_t)(j0 + 4 * cq + 3) * Dn + k];
            *(float4*)&wt1[k * WT1_PITCH + 4 * cq] = make_float4(w0, w1, w2, w3);
        }
    }
    __syncthreads();

    const int r0 = wp * 2;          // 2 rows per thread
    const int c0 = lane * 4;
    ull A[2][6];
#pragma unroll
    for (int r = 0; r < 2; r++)
#pragma unroll
        for (int q = 0; q < 6; q++) A[r][q] = 0ULL;

#pragma unroll 8
    for (int k = 0; k < 128; k++) {
        ulonglong2 uw = *(ulonglong2*)&wt1[k * WT1_PITCH + c0];
        ull wa0 = uw.x & AMASK, wa1 = uw.y & AMASK;
#pragma unroll
        for (int r = 0; r < 2; r++) {
            float4 h = xs[(r0 + r) * 128 + k];
            ull vv = pk2(h.x), mm = pk2(h.y), rr = pk2(h.z);
            fma2(A[r][0], vv, uw.x); fma2(A[r][1], vv, uw.y);
            fma2(A[r][2], mm, uw.x); fma2(A[r][3], mm, uw.y);
            fma2(A[r][4], rr, wa0);  fma2(A[r][5], rr, wa1);
        }
    }

    float4 b4 = *(const float4*)&bias[j0 + c0];
#pragma unroll
    for (int r = 0; r < 2; r++) {
        size_t ob = (size_t)(tb0 + r0 + r) * G4H + j0 + c0;
        float2 v01 = unp(A[r][0]), v23 = unp(A[r][1]);
        float2 m01 = unp(A[r][2]), m23 = unp(A[r][3]);
        float2 q01 = unp(A[r][4]), q23 = unp(A[r][5]);
        g_pxq[ob + 0] = make_float4(v01.x + b4.x, m01.x + b4.x, q01.x, 0.f);
        g_pxq[ob + 1] = make_float4(v01.y + b4.y, m01.y + b4.y, q01.y, 0.f);
        g_pxq[ob + 2] = make_float4(v23.x + b4.z, m23.x + b4.z, q23.x, 0.f);
        g_pxq[ob + 3] = make_float4(v23.y + b4.w, m23.y + b4.w, q23.y, 0.f);
    }
}

// ---------------------------------------------------------------------------
// Phase 2: persistent recurrent interval-LSTM, single-trip tagged exchange.
// R14 VERBATIM (proven 4128us): 128 CTAs = 16 groups x 8 CTAs.
// Each h element crosses L2 as THREE self-validating relaxed b64 words
// {tag|v},{tag|m},{tag|r}; consumer issues all 12 loads at once, spins
// per-word until tag==t. gbuf parity-buffered -> ONE __syncthreads per step.
// GEMM: warp (rp,kq) = rows {2rp,2rp+1} x 128 cols x 64-k quarter.
// ---------------------------------------------------------------------------
#define WT2_PITCH 132

struct I3 { float v, l, u; };

__device__ __forceinline__ float sigm(float x)   { return 1.0f / (1.0f + __expf(-x)); }
__device__ __forceinline__ float tanh_f(float x) { return 1.0f - 2.0f / (1.0f + __expf(2.0f * x)); }
__device__ __forceinline__ I3 imul(I3 a, I3 b) {
    float p1 = a.l * b.l, p2 = a.l * b.u, p3 = a.u * b.l, p4 = a.u * b.u;
    I3 o;
    o.v = a.v * b.v;
    o.l = fminf(fminf(p1, p2), fminf(p3, p4));
    o.u = fmaxf(fmaxf(p1, p2), fmaxf(p3, p4));
    return o;
}

#define SM_WT_BYTES   (256 * WT2_PITCH * 4)            // 135168
#define SM_HVM_BYTES  (4 * 256 * 16)                   // 16384
#define SM_HR_BYTES   (4 * 256 * 8)                    // 8192
#define SM_GBUF_BYTES (2 * 4 * 4 * 128 * 16)           // 65536 ([parity][kq][row][col])
#define SM2_TOTAL     (SM_WT_BYTES + SM_HVM_BYTES + SM_HR_BYTES + SM_GBUF_BYTES) // 225280

__global__ void __launch_bounds__(256, 1)
lstm_phase2(const float* __restrict__ Whh, float* __restrict__ out)
{
    extern __shared__ char sm2c[];
    float*      wt   = (float*)sm2c;                                    // [256][132]
    ulonglong2* hvm  = (ulonglong2*)(sm2c + SM_WT_BYTES);               // [4][256] {v,v,m,m}
    ull*        hr   = (ull*)(sm2c + SM_WT_BYTES + SM_HVM_BYTES);       // [4][256] {r,r}
    float4*     gbuf = (float4*)(sm2c + SM_WT_BYTES + SM_HVM_BYTES + SM_HR_BYTES); // [2][4][4][128]

    const int tid  = threadIdx.x;
    const int lane = tid & 31;
    const int wp   = tid >> 5;
    const int grp  = blockIdx.x >> 3;
    const int cta  = blockIdx.x & 7;
    const int hbase = cta * 32;
    const int bbase = grp * 4;

    // W_hh slice transposed: wt[k][c], c = g*32 + j
#pragma unroll
    for (int i = 0; i < 4; i++) {
        int cq = wp + 8 * i;
#pragma unroll
        for (int j = 0; j < 8; j++) {
            int k = j * 32 + lane;
            float w[4];
#pragma unroll
            for (int q = 0; q < 4; q++) {
                int c = 4 * cq + q;
                int g = c >> 5, jj = c & 31;
                w[q] = Whh[(size_t)(g * 256 + hbase + jj) * Hn + k];
            }
            *(float4*)&wt[k * WT2_PITCH + 4 * cq] = make_float4(w[0], w[1], w[2], w[3]);
        }
    }
    for (int i = tid; i < 4 * 256; i += 256) {
        hvm[i] = make_ulonglong2(0ULL, 0ULL);
        hr[i]  = 0ULL;
    }
    __syncthreads();

    const int rp   = wp >> 2;       // row pair 0..1
    const int kq   = wp & 3;        // k quarter 0..3
    const int kb   = kq * 64;
    const int c0   = lane * 4;      // 4 cols per thread
    const int erow = tid >> 5;      // elementwise row (tid<128)
    const int ej   = tid & 31;
    float cv = 0.f, cl = 0.f, cu = 0.f;

    // t-invariant pull geometry: this warp's private region is
    // slices {2kq,2kq+1} x rows {2rp,2rp+1}, 4 elements per lane.
    int off[4], srow[4], skk[4];
#pragma unroll
    for (int p = 0; p < 4; p++) {
        int idx = p * 32 + lane;            // 0..127
        int s   = idx >> 6;                 // slice select 0..1
        int rr  = (idx >> 5) & 1;           // row select 0..1
        int j   = idx & 31;
        off[p]  = (2 * kq + s) * 128 + (2 * rp + rr) * 32 + j;
        srow[p] = 2 * rp + rr;
        skk[p]  = (2 * kq + s) * 32 + j;
    }
    const ull* baseV[2] = { &g_sv[0][grp][0][0], &g_sv[1][grp][0][0] };
    const ull* baseM[2] = { &g_sm[0][grp][0][0], &g_sm[1][grp][0][0] };
    const ull* baseR[2] = { &g_sr[0][grp][0][0], &g_sr[1][grp][0][0] };

    const size_t PLANE = (size_t)Bn * Tn * Hn;

    for (int t = 0; t < Tn; t++) {
        // Px prefetch (epilogue warps only; hides DRAM under poll/GEMM)
        float4 P[4];
        if (tid < 128) {
            size_t base = ((size_t)t * 64 + bbase + erow) * G4H + hbase + ej;
#pragma unroll
            for (int g = 0; g < 4; g++) P[g] = g_pxq[base + g * 256];
        }

        if (t > 0) {
            // Single-trip poll+pull: 12 independent relaxed loads (full MLP),
            // then spin per word until its tag == t. 8B relaxed atomics are
            // untorn; validity is in-band -> no fences, no ordering needed.
            // Replay-safe: per-slot tags are monotone within a launch, and
            // the step-(t-2) poll of the same slot forces a this-launch
            // overwrite before a stale tag could ever equal the wanted t.
            const unsigned want = (unsigned)t;
            const int par = (t - 1) & 1;
            const ull* sv = baseV[par];
            const ull* sm = baseM[par];
            const ull* sr = baseR[par];
            ull vv[4], vm[4], vr[4];
#pragma unroll
            for (int p = 0; p < 4; p++) {
                vv[p] = ld_rx64(sv + off[p]);
                vm[p] = ld_rx64(sm + off[p]);
                vr[p] = ld_rx64(sr + off[p]);
            }
#pragma unroll
            for (int p = 0; p < 4; p++) {
                while ((unsigned)(vv[p] >> 32) != want) vv[p] = ld_rx64(sv + off[p]);
                while ((unsigned)(vm[p] >> 32) != want) vm[p] = ld_rx64(sm + off[p]);
                while ((unsigned)(vr[p] >> 32) != want) vr[p] = ld_rx64(sr + off[p]);
            }
#pragma unroll
            for (int p = 0; p < 4; p++) {
                ulonglong2 pk;
                pk.x = pk2u((unsigned)vv[p]);
                pk.y = pk2u((unsigned)vm[p]);
                hvm[srow[p] * 256 + skk[p]] = pk;
                hr[srow[p] * 256 + skk[p]]  = pk2u((unsigned)vr[p]);
            }
            __syncwarp();   // pull visible warp-wide before GEMM
        }

        // GEMM: warp covers rows {2rp, 2rp+1} x 128 cols x k in [kb, kb+64)
        ull A[2][6];
#pragma unroll
        for (int r = 0; r < 2; r++)
#pragma unroll
            for (int q = 0; q < 6; q++) A[r][q] = 0ULL;

#pragma unroll 8
        for (int kk = 0; kk < 64; kk++) {
            const int k = kb + kk;
            ulonglong2 w2 = *(const ulonglong2*)&wt[k * WT2_PITCH + c0];
            ull wa0 = w2.x & AMASK, wa1 = w2.y & AMASK;
#pragma unroll
            for (int r2 = 0; r2 < 2; r2++) {
                const int r = rp * 2 + r2;
                ulonglong2 h2 = hvm[r * 256 + k];
                ull h3 = hr[r * 256 + k];
                fma2(A[r2][0], h2.x, w2.x); fma2(A[r2][1], h2.x, w2.y);
                fma2(A[r2][2], h2.y, w2.x); fma2(A[r2][3], h2.y, w2.y);
                fma2(A[r2][4], h3, wa0);    fma2(A[r2][5], h3, wa1);
            }
        }

        // Partials into parity buffer; warp (rp,kq) owns disjoint slot rows.
        float4* gb = gbuf + (size_t)(t & 1) * 4 * 4 * 128;
        {
            float4* gs = gb + ((size_t)kq * 4 + rp * 2) * 128;
#pragma unroll
            for (int r2 = 0; r2 < 2; r2++) {
                float2 v01 = unp(A[r2][0]), v23 = unp(A[r2][1]);
                float2 m01 = unp(A[r2][2]), m23 = unp(A[r2][3]);
                float2 q01 = unp(A[r2][4]), q23 = unp(A[r2][5]);
                float4* gp = gs + r2 * 128 + c0;
                gp[0] = make_float4(v01.x, m01.x, q01.x, 0.f);
                gp[1] = make_float4(v01.y, m01.y, q01.y, 0.f);
                gp[2] = make_float4(v23.x, m23.x, q23.x, 0.f);
                gp[3] = make_float4(v23.y, m23.y, q23.y, 0.f);
            }
        }
        __syncthreads();   // the ONLY barrier: partials visible to epilogue

        if (tid < 128) {
            I3 gate[4];
#pragma unroll
            for (int g = 0; g < 4; g++) {
                int col = g * 32 + ej;
                float v = P[g].x, m = P[g].y, rr = P[g].z;
#pragma unroll
                for (int s = 0; s < 4; s++) {          // sum 4 k-quarters
                    float4 gs = gb[((size_t)s * 4 + erow) * 128 + col];
                    v += gs.x; m += gs.y; rr += gs.z;
                }
                gate[g].v = v; gate[g].l = m - rr; gate[g].u = m + rr;
            }
            I3 ig = { sigm(gate[0].v),   sigm(gate[0].l),   sigm(gate[0].u) };
            I3 fg = { sigm(gate[1].v),   sigm(gate[1].l),   sigm(gate[1].u) };
            I3 gg = { tanh_f(gate[2].v), tanh_f(gate[2].l), tanh_f(gate[2].u) };
            I3 og = { sigm(gate[3].v),   sigm(gate[3].l),   sigm(gate[3].u) };

            I3 cold = { cv, cl, cu };
            I3 fc  = imul(fg, cold);
            I3 igg = imul(ig, gg);
            I3 cn  = { fc.v + igg.v, fc.l + igg.l, fc.u + igg.u };
            I3 tc  = { tanh_f(cn.v), tanh_f(cn.l), tanh_f(cn.u) };
            I3 hn  = imul(og, tc);
            cv = cn.v; cl = cn.l; cu = cn.u;

            size_t ob = ((size_t)(bbase + erow) * Tn + t) * Hn + hbase + ej;
            out[ob]             = hn.v;
            out[ob + PLANE]     = hn.l;
            out[ob + 2 * PLANE] = hn.u;

            if (t < Tn - 1) {
                // Publish h(t): three self-validating words, tag = t+1.
                int slot = erow * 32 + ej;
                float hm  = 0.5f * (hn.l + hn.u);
                float hrr = 0.5f * (hn.u - hn.l);
                ull tag = (ull)(unsigned)(t + 1) << 32;
                st_rx64(&g_sv[t & 1][grp][cta][slot], tag | __float_as_uint(hn.v));
                st_rx64(&g_sm[t & 1][grp][cta][slot], tag | __float_as_uint(hm));
                st_rx64(&g_sr[t & 1][grp][cta][slot], tag | __float_as_uint(hrr));
            }
        }
        // no end-of-step barrier: gbuf is parity-buffered; hvm/hr are
        // warp-private; warps 4-7 may run ahead into step t+1.
    }
}

// ---------------------------------------------------------------------------
extern "C" void kernel_launch(void* const* d_in, const int* in_sizes, int n_in,
                              void* d_out, int out_size)
{
    const float* xv   = (const float*)d_in[0];
    const float* xl   = (const float*)d_in[1];
    const float* xu   = (const float*)d_in[2];
    const float* Wih  = (const float*)d_in[3];
    const float* Whh  = (const float*)d_in[4];
    const float* bias = (const float*)d_in[5];
    float* out = (float*)d_out;

    const int smem1 = 16 * 128 * (int)sizeof(float4)
                    + 128 * WT1_PITCH * (int)sizeof(float);     // 100352 -> 2 CTA/SM

    cudaFuncSetAttribute(lstm_phase1, cudaFuncAttributeMaxDynamicSharedMemorySize, smem1);
    cudaFuncSetAttribute(lstm_phase2, cudaFuncAttributeMaxDynamicSharedMemorySize, SM2_TOTAL);

    // Phase 1: 2048 row-blocks (16 rows each) x 8 col-blocks (128 cols each)
    lstm_phase1<<<dim3(2048, 8, 1), 256, smem1>>>(xv, xl, xu, Wih, bias);
    lstm_phase2<<<128, 256, SM2_TOTAL>>>(Whh, out);
}